// round 10
// baseline (speedup 1.0000x reference)
#include <cuda_runtime.h>
#include <cstdint>

// ---------------- scratch (allocation-free: __device__ globals) ----------------
#define T_TOK 8192
__device__ float g_qa [T_TOK*1536];   // after wq_a (+rmsnorm in-place, tf32-rounded)
__device__ float g_q  [T_TOK*3072];   // after wq_b (full fp32, attention input)
__device__ float g_kva[T_TOK*576];    // after wkv_a
__device__ float g_kvn[T_TOK*512];    // normalized kv latent (tf32-rounded)
__device__ float g_kpe[T_TOK*64];     // roped k_pe
__device__ float g_kv [T_TOK*4096];   // after wkv_b (full fp32)
__device__ float g_ao [T_TOK*2048];   // attention output (tf32-rounded)
__device__ float g_xr [T_TOK*2048];   // x rounded to tf32
__device__ float g_wr [15335424];     // all 5 weight matrices rounded to tf32

#define WQA_OFF   0
#define WQB_OFF   3145728
#define WKVA_OFF  7864320
#define WKVB_OFF  9043968
#define WO_OFF    11141120

// ---------------- PTX helpers (arch-generic: sm_80+) ----------------
__device__ __forceinline__ void cp_async16(void* dst, const void* src) {
    unsigned s = (unsigned)__cvta_generic_to_shared(dst);
    asm volatile("cp.async.cg.shared.global [%0], [%1], 16;\n" :: "r"(s), "l"(src));
}
__device__ __forceinline__ void cp_commit() { asm volatile("cp.async.commit_group;\n"); }
template<int N> __device__ __forceinline__ void cp_wait() {
    asm volatile("cp.async.wait_group %0;\n" :: "n"(N));
}
__device__ __forceinline__ float tf32r(float x) {
    uint32_t r;
    asm("cvt.rna.tf32.f32 %0, %1;" : "=r"(r) : "f"(x));
    return __uint_as_float(r);
}
__device__ __forceinline__ void mma1688(float* d, const uint32_t* a, const uint32_t* b) {
    asm volatile(
        "mma.sync.aligned.m16n8k8.row.col.f32.tf32.tf32.f32 "
        "{%0,%1,%2,%3}, {%4,%5,%6,%7}, {%8,%9}, {%0,%1,%2,%3};"
        : "+f"(d[0]), "+f"(d[1]), "+f"(d[2]), "+f"(d[3])
        : "r"(a[0]), "r"(a[1]), "r"(a[2]), "r"(a[3]), "r"(b[0]), "r"(b[1]));
}
__device__ __forceinline__ void ldsm_x4(uint32_t a, uint32_t* r) {
    asm volatile("ldmatrix.sync.aligned.m8n8.x4.shared.b16 {%0,%1,%2,%3}, [%4];"
        : "=r"(r[0]), "=r"(r[1]), "=r"(r[2]), "=r"(r[3]) : "r"(a));
}

// ---------------- tf32 mma.sync GEMM: C[M,N] = A[M,K] @ W[N,K]^T + bias[N] ----
// BM=BN=128, BK=32, 128 threads (4 warps 2x2), warp tile 64x64 (4x8 m16n8k8).
// 64x64 warp tiles cut smem read bytes/MAC by 33% vs 64x32 -> smem (1536 cyc)
// now fits under the tensor floor (2048 cyc) per K-tile pair.
// Inputs MUST be pre-rounded to tf32. 3-stage cp.async pipeline, ONE barrier
// per K-tile; ldmatrix.x4 fragment loads double-buffered across kk.
#define GLDS 36
#define TILE_F (128 * GLDS)               // floats per tile (A or B)
#define TILE_BYTES (TILE_F * 4)
#define STG_F  (2 * TILE_F)               // floats per stage (A+B)
#define STG_BYTES (STG_F * 4)
#define GEMM_SMEM (3 * STG_BYTES + 512)   // 111104 B

__global__ __launch_bounds__(128, 2) void gemm_mma(
    const float* __restrict__ A, const float* __restrict__ W,
    const float* __restrict__ bias, float* __restrict__ C,
    int M, int N, int K)
{
    extern __shared__ float smem[];
    float* sBias = smem + 3 * STG_F;
    const uint32_t smem_u = (uint32_t)__cvta_generic_to_shared(smem);

    const int tid = threadIdx.x, warp = tid >> 5, lane = tid & 31;
    const int gid = lane >> 2, tig = lane & 3;
    const int bm = blockIdx.y * 128, bn = blockIdx.x * 128;
    const int wm = (warp >> 1) * 64, wn = (warp & 1) * 64;
    const int KT = K / 32;

    {
        int c = bn + tid;
        sBias[tid] = (c < N) ? bias[c] : 0.0f;
    }

    float acc[4][8][4];
#pragma unroll
    for (int i = 0; i < 4; i++)
#pragma unroll
        for (int j = 0; j < 8; j++)
#pragma unroll
            for (int r = 0; r < 4; r++) acc[i][j][r] = 0.0f;

    // loader: 2048 16B-chunks per stage (A:1024, B:1024), 16 per thread
    const int lrow = tid >> 3, lc16 = tid & 7;
    auto load_stage = [&](int kt) {
        float* st = smem + (kt % 3) * STG_F;
        const int k0 = kt * 32;
#pragma unroll
        for (int i = 0; i < 8; i++) {
            const int row = lrow + i * 16;
            cp_async16(st + row * GLDS + lc16 * 4,
                       A + (size_t)(bm + row) * K + k0 + lc16 * 4);
            int rB = bn + row; if (rB >= N) rB = N - 1;   // clamp; junk cols never stored
            cp_async16(st + TILE_F + row * GLDS + lc16 * 4,
                       W + (size_t)rB * K + k0 + lc16 * 4);
        }
        cp_commit();
    };

    // per-lane ldmatrix base offsets (bytes, within a stage)
    // A x4 (tile i): rows wm+i*16+(lane&15), k-word ((lane>>4)<<2)
    const uint32_t aOff = 4 * ((wm + (lane & 15)) * GLDS + ((lane >> 4) << 2));
    // B x4 (pair p): covers n8-tiles 2p,2p+1; rows wn+p*16+((lane>>4)<<3)+(lane&7)
    const uint32_t bOff = TILE_BYTES
        + 4 * ((wn + ((lane >> 4) << 3) + (lane & 7)) * GLDS + (((lane >> 3) & 1) << 2));

    load_stage(0);
    load_stage(1);

    for (int kt = 0; kt < KT; kt++) {
        if (kt + 1 < KT) cp_wait<1>(); else cp_wait<0>();
        __syncthreads();                       // stage kt visible; stage (kt+2)%3 free
        if (kt + 2 < KT) load_stage(kt + 2);

        const uint32_t stg = smem_u + (kt % 3) * STG_BYTES;
        const uint32_t aB = stg + aOff;
        const uint32_t bB = stg + bOff;

        uint32_t Af[2][4][4], Bq[2][4][4];
#pragma unroll
        for (int i = 0; i < 4; i++) ldsm_x4(aB + (uint32_t)(i * 16 * GLDS) * 4, Af[0][i]);
#pragma unroll
        for (int p = 0; p < 4; p++) ldsm_x4(bB + (uint32_t)(p * 16 * GLDS) * 4, Bq[0][p]);

#pragma unroll
        for (int kk = 0; kk < 4; kk++) {
            const int cur = kk & 1;
            if (kk < 3) {   // prefetch kk+1 fragments while cur's MMAs drain
                const uint32_t ko = (uint32_t)((kk + 1) * 8) * 4;
#pragma unroll
                for (int i = 0; i < 4; i++)
                    ldsm_x4(aB + ko + (uint32_t)(i * 16 * GLDS) * 4, Af[cur ^ 1][i]);
#pragma unroll
                for (int p = 0; p < 4; p++)
                    ldsm_x4(bB + ko + (uint32_t)(p * 16 * GLDS) * 4, Bq[cur ^ 1][p]);
            }
#pragma unroll
            for (int i = 0; i < 4; i++)
#pragma unroll
                for (int j = 0; j < 8; j++)
                    mma1688(acc[i][j], Af[cur][i], &Bq[cur][j >> 1][(j & 1) * 2]);
        }
    }

    // epilogue: direct float2 stores (+bias)
#pragma unroll
    for (int i = 0; i < 4; i++) {
        const int r0 = bm + wm + i * 16 + gid;
        const int r1 = r0 + 8;
#pragma unroll
        for (int j = 0; j < 8; j++) {
            const int c = wn + j * 8 + tig * 2;
            if (bn + c < N) {
                const float b0 = sBias[c], b1 = sBias[c + 1];
                float2 v0 = {acc[i][j][0] + b0, acc[i][j][1] + b1};
                float2 v1 = {acc[i][j][2] + b0, acc[i][j][3] + b1};
                *(float2*)(C + (size_t)r0 * N + bn + c) = v0;
                *(float2*)(C + (size_t)r1 * N + bn + c) = v1;
            }
        }
    }
}

// ---------------- tf32 rounding prepass (float4 grid-stride) ----------------
__global__ __launch_bounds__(256) void round_tf32_k(
    const float* __restrict__ in, float* __restrict__ out, int n)
{
    int i = (blockIdx.x * 256 + threadIdx.x) * 4;
    if (i < n) {
        float4 v = *(const float4*)(in + i);
        v.x = tf32r(v.x); v.y = tf32r(v.y); v.z = tf32r(v.z); v.w = tf32r(v.w);
        *(float4*)(out + i) = v;
    }
}

// ---------------- RMSNorm (in-place; output tf32-rounded for next GEMM) ------
__global__ __launch_bounds__(256) void rmsnorm_inplace(
    float* __restrict__ data, const float* __restrict__ w, int W)
{
    const int t = blockIdx.x, tid = threadIdx.x;
    float* p = data + (size_t)t * W;
    const int W4 = W >> 2;
    float ss = 0.f;
    for (int i = tid; i < W4; i += 256) {
        float4 v = ((const float4*)p)[i];
        ss += v.x * v.x + v.y * v.y + v.z * v.z + v.w * v.w;
    }
    __shared__ float red[256];
    red[tid] = ss; __syncthreads();
    for (int w2 = 128; w2 > 0; w2 >>= 1) {
        if (tid < w2) red[tid] += red[tid + w2];
        __syncthreads();
    }
    const float inv = rsqrtf(red[0] / (float)W + 1.1920929e-7f);
    for (int i = tid; i < W4; i += 256) {
        float4 v = ((const float4*)p)[i];
        const float4 g = ((const float4*)w)[i];
        v.x = tf32r(v.x * inv * g.x); v.y = tf32r(v.y * inv * g.y);
        v.z = tf32r(v.z * inv * g.z); v.w = tf32r(v.w * inv * g.w);
        ((float4*)p)[i] = v;
    }
}

// ---------------- kv_a post-process: rmsnorm(512, rounded) + rope(last 64) ---
__global__ __launch_bounds__(128) void kv_prep(
    const float* __restrict__ kva, const float* __restrict__ knw,
    const float* __restrict__ cosb, const float* __restrict__ sinb,
    float* __restrict__ kvn, float* __restrict__ kpe, int S)
{
    const int t = blockIdx.x, tid = threadIdx.x;
    const int s = t % S;
    const float* src = kva + (size_t)t * 576;
    float ss = 0.f;
    for (int i = tid; i < 512; i += 128) { float v = src[i]; ss += v * v; }
    __shared__ float red[128];
    red[tid] = ss; __syncthreads();
    for (int w2 = 64; w2 > 0; w2 >>= 1) {
        if (tid < w2) red[tid] += red[tid + w2];
        __syncthreads();
    }
    const float inv = rsqrtf(red[0] / 512.0f + 1.1920929e-7f);
    for (int i = tid; i < 512; i += 128)
        kvn[(size_t)t * 512 + i] = tf32r(src[i] * inv * knw[i]);
    if (tid < 32) {
        const int j = tid;
        const float c = cosb[s * 32 + j], sn = sinb[s * 32 + j];
        const float x0 = src[512 + 2 * j], x1 = src[512 + 2 * j + 1];
        kpe[(size_t)t * 64 + 2 * j]     = x0 * c  - x1 * sn;
        kpe[(size_t)t * 64 + 2 * j + 1] = x0 * sn + x1 * c;
    }
}

// ---------------- per-token attention (output tf32-rounded for wo GEMM) ------
#define ATT_SCALE 0.07216878364870322f  // (128+64)^-0.5
__global__ __launch_bounds__(128) void attn_kernel(
    const float* __restrict__ q, const float* __restrict__ kv,
    const float* __restrict__ kpe, const float* __restrict__ cosb,
    const float* __restrict__ sinb, float* __restrict__ out, int S)
{
    const int t = blockIdx.x, tid = threadIdx.x;
    const int s = t % S;
    __shared__ float qs[3072];
    __shared__ float kvs[16 * 260];
    __shared__ float kp[64];
    __shared__ float sc[16][17];

    const float* qg = q + (size_t)t * 3072;
    for (int i = tid; i < 768; i += 128) ((float4*)qs)[i] = ((const float4*)qg)[i];
    const float* kvg = kv + (size_t)t * 4096;
    for (int i = tid; i < 1024; i += 128) {
        int g = i >> 6, c = i & 63;
        *(float4*)&kvs[g * 260 + c * 4] = *(const float4*)(kvg + g * 256 + c * 4);
    }
    if (tid < 16) ((float4*)kp)[tid] = ((const float4*)(kpe + (size_t)t * 64))[tid];
    __syncthreads();

    for (int p = tid; p < 512; p += 128) {
        const int h = p >> 5, j = p & 31;
        const float c = cosb[s * 32 + j], sn = sinb[s * 32 + j];
        const int i0 = h * 192 + 128 + 2 * j;
        const float x0 = qs[i0], x1 = qs[i0 + 1];
        qs[i0]     = x0 * c  - x1 * sn;
        qs[i0 + 1] = x0 * sn + x1 * c;
    }
    __syncthreads();

    {
        const int h = tid >> 3, g0 = tid & 7, g1 = g0 + 8;
        const float* qh = &qs[h * 192];
        const float* k0 = &kvs[g0 * 260];
        const float* k1 = &kvs[g1 * 260];
        float a0 = 0.f, a1 = 0.f;
#pragma unroll 8
        for (int d = 0; d < 128; d++) { const float qd = qh[d]; a0 += qd * k0[d]; a1 += qd * k1[d]; }
        float pe = 0.f;
        const float* qp = &qs[h * 192 + 128];
#pragma unroll 8
        for (int d = 0; d < 64; d++) pe += qp[d] * kp[d];
        sc[h][g0] = (a0 + pe) * ATT_SCALE;
        sc[h][g1] = (a1 + pe) * ATT_SCALE;
    }
    __syncthreads();

    if (tid < 16) {
        float m = -1e30f;
#pragma unroll
        for (int g = 0; g < 16; g++) m = fmaxf(m, sc[tid][g]);
        float sum = 0.f;
#pragma unroll
        for (int g = 0; g < 16; g++) { const float e = expf(sc[tid][g] - m); sc[tid][g] = e; sum += e; }
        const float r = 1.f / sum;
#pragma unroll
        for (int g = 0; g < 16; g++) sc[tid][g] *= r;
    }
    __syncthreads();

    for (int o = tid; o < 2048; o += 128) {
        const int h = o >> 7, d = o & 127;
        float acc = 0.f;
#pragma unroll
        for (int g = 0; g < 16; g++) acc += sc[h][g] * kvs[g * 260 + 128 + d];
        out[(size_t)t * 2048 + o] = tf32r(acc);
    }
}

// ---------------- host launcher ----------------
static inline void launch_gemm(const float* A, const float* W, const float* bias,
                               float* C, int M, int N, int K)
{
    dim3 grid((N + 127) / 128, M / 128);
    gemm_mma<<<grid, 128, GEMM_SMEM>>>(A, W, bias, C, M, N, K);
}
static inline void launch_round(const float* in, float* out, int n)
{
    round_tf32_k<<<(n / 4 + 255) / 256, 256>>>(in, out, n);
}

extern "C" void kernel_launch(void* const* d_in, const int* in_sizes, int n_in,
                              void* d_out, int out_size)
{
    const float* x     = (const float*)d_in[0];
    const float* fcos  = (const float*)d_in[1];
    const float* fsin  = (const float*)d_in[2];
    const float* wqa   = (const float*)d_in[3];
    const float* wqab  = (const float*)d_in[4];
    const float* qnw   = (const float*)d_in[5];
    const float* wqb   = (const float*)d_in[6];
    const float* wqbb  = (const float*)d_in[7];
    const float* wkva  = (const float*)d_in[8];
    const float* wkvab = (const float*)d_in[9];
    const float* kvnw  = (const float*)d_in[10];
    const float* wkvb  = (const float*)d_in[11];
    const float* wkvbb = (const float*)d_in[12];
    const float* wo    = (const float*)d_in[13];
    const float* wob   = (const float*)d_in[14];
    float* out = (float*)d_out;

    const int T = in_sizes[0] / 2048;   // B*S tokens (8192)
    const int S = in_sizes[1] / 32;     // 2048

    float *qa, *qq, *kva, *kvn, *kpe, *kv, *ao, *xr, *wr;
    cudaGetSymbolAddress((void**)&qa,  g_qa);
    cudaGetSymbolAddress((void**)&qq,  g_q);
    cudaGetSymbolAddress((void**)&kva, g_kva);
    cudaGetSymbolAddress((void**)&kvn, g_kvn);
    cudaGetSymbolAddress((void**)&kpe, g_kpe);
    cudaGetSymbolAddress((void**)&kv,  g_kv);
    cudaGetSymbolAddress((void**)&ao,  g_ao);
    cudaGetSymbolAddress((void**)&xr,  g_xr);
    cudaGetSymbolAddress((void**)&wr,  g_wr);

    cudaFuncSetAttribute(gemm_mma, cudaFuncAttributeMaxDynamicSharedMemorySize, GEMM_SMEM);

    // prepass: round x + all weights to tf32 (bit-exact with per-fragment cvt)
    launch_round(x,    xr,             T * 2048);
    launch_round(wqa,  wr + WQA_OFF,   1536 * 2048);
    launch_round(wqb,  wr + WQB_OFF,   3072 * 1536);
    launch_round(wkva, wr + WKVA_OFF,  576 * 2048);
    launch_round(wkvb, wr + WKVB_OFF,  4096 * 512);
    launch_round(wo,   wr + WO_OFF,    2048 * 2048);

    // q path
    launch_gemm(xr,  wr + WQA_OFF,  wqab,  qa,  T, 1536, 2048);
    rmsnorm_inplace<<<T, 256>>>(qa, qnw, 1536);
    launch_gemm(qa,  wr + WQB_OFF,  wqbb,  qq,  T, 3072, 1536);
    // kv path
    launch_gemm(xr,  wr + WKVA_OFF, wkvab, kva, T, 576,  2048);
    kv_prep<<<T, 128>>>(kva, kvnw, fcos, fsin, kvn, kpe, S);
    launch_gemm(kvn, wr + WKVB_OFF, wkvbb, kv,  T, 4096, 512);
    // attention + output projection
    attn_kernel<<<T, 128>>>(qq, kv, kpe, fcos, fsin, ao, S);
    launch_gemm(ao,  wr + WO_OFF,   wob,   out, T, 2048, 2048);
}

// round 12
// speedup vs baseline: 1.1837x; 1.1837x over previous
#include <cuda_runtime.h>
#include <cuda_fp16.h>
#include <cstdint>

// ---------------- scratch (allocation-free: __device__ globals) ----------------
#define T_TOK 8192
__device__ float  g_qa [T_TOK*1536];   // wq_a output (fp32)
__device__ __half g_qah[T_TOK*1536];   // rmsnorm(qa) in fp16
__device__ float  g_q  [T_TOK*3072];   // wq_b output (fp32, attention input)
__device__ float  g_kva[T_TOK*576];    // wkv_a output
__device__ __half g_kvn[T_TOK*512];    // normalized kv latent (fp16)
__device__ float  g_kpe[T_TOK*64];     // roped k_pe
__device__ float  g_kv [T_TOK*4096];   // wkv_b output (fp32)
__device__ __half g_ao [T_TOK*2048];   // attention output (fp16)
__device__ __half g_xh [T_TOK*2048];   // x in fp16
__device__ __half g_wh [15335424];     // all 5 weight matrices in fp16

#define WQA_OFF   0
#define WQB_OFF   3145728
#define WKVA_OFF  7864320
#define WKVB_OFF  9043968
#define WO_OFF    11141120

// ---------------- PTX helpers (arch-generic: sm_80+) ----------------
__device__ __forceinline__ void cp_async16(void* dst, const void* src) {
    unsigned s = (unsigned)__cvta_generic_to_shared(dst);
    asm volatile("cp.async.cg.shared.global [%0], [%1], 16;\n" :: "r"(s), "l"(src));
}
__device__ __forceinline__ void cp_commit() { asm volatile("cp.async.commit_group;\n"); }
template<int N> __device__ __forceinline__ void cp_wait() {
    asm volatile("cp.async.wait_group %0;\n" :: "n"(N));
}
__device__ __forceinline__ void mma16816(float* d, const uint32_t* a, const uint32_t* b) {
    asm volatile(
        "mma.sync.aligned.m16n8k16.row.col.f32.f16.f16.f32 "
        "{%0,%1,%2,%3}, {%4,%5,%6,%7}, {%8,%9}, {%0,%1,%2,%3};"
        : "+f"(d[0]), "+f"(d[1]), "+f"(d[2]), "+f"(d[3])
        : "r"(a[0]), "r"(a[1]), "r"(a[2]), "r"(a[3]), "r"(b[0]), "r"(b[1]));
}
__device__ __forceinline__ void ldsm_x4(uint32_t a, uint32_t* r) {
    asm volatile("ldmatrix.sync.aligned.m8n8.x4.shared.b16 {%0,%1,%2,%3}, [%4];"
        : "=r"(r[0]), "=r"(r[1]), "=r"(r[2]), "=r"(r[3]) : "r"(a));
}

// ---------------- fp16 mma.sync GEMM: C[M,N] = A[M,K] @ W[N,K]^T + bias[N] ---
// BM=BN=128, BK=64, 256 threads (8 warps 2x4), warp tile 64x32 (4x4 m16n8k16).
// fp32 accumulate. A,W are fp16 (same 10-bit mantissa as tf32 -> same rounding
// error, 2x MAC rate, half the bytes). Row stride 72 halves (144B) keeps every
// 8-row ldmatrix phase conflict-free. 3-stage cp.async pipeline, one barrier
// per K-tile; fragment double-buffering across the 4 k16 sub-steps.
#define ROWB 144                          // bytes per smem row (72 halves)
#define TILE_BYTES (128 * ROWB)           // 18432 B per tile (A or B)
#define STG_BYTES (2 * TILE_BYTES)        // 36864 B per stage
#define GEMM_SMEM (3 * STG_BYTES + 512)   // 111104 B

__global__ __launch_bounds__(256, 2) void gemm_mma(
    const __half* __restrict__ A, const __half* __restrict__ W,
    const float* __restrict__ bias, float* __restrict__ C,
    int M, int N, int K)
{
    extern __shared__ char smem[];
    float* sBias = (float*)(smem + 3 * STG_BYTES);
    const uint32_t smem_u = (uint32_t)__cvta_generic_to_shared(smem);

    const int tid = threadIdx.x, warp = tid >> 5, lane = tid & 31;
    const int gid = lane >> 2, tig = lane & 3;
    const int bm = blockIdx.y * 128, bn = blockIdx.x * 128;
    const int wm = (warp >> 2) * 64, wn = (warp & 3) * 32;
    const int KT = K / 64;

    if (tid < 128) {
        int c = bn + tid;
        sBias[tid] = (c < N) ? bias[c] : 0.0f;
    }

    float acc[4][4][4];
#pragma unroll
    for (int i = 0; i < 4; i++)
#pragma unroll
        for (int j = 0; j < 4; j++)
#pragma unroll
            for (int r = 0; r < 4; r++) acc[i][j][r] = 0.0f;

    // loader: per stage 2048 16B-chunks (A:1024, B:1024), 8 per thread.
    // row has 8 chunks of 8 halves (64 halves = 128B payload, 144B stride).
    const int lrow = tid >> 3, lc16 = tid & 7;
    auto load_stage = [&](int kt) {
        char* st = smem + (kt % 3) * STG_BYTES;
        const int k0 = kt * 64;
#pragma unroll
        for (int i = 0; i < 4; i++) {
            const int row = lrow + i * 32;
            cp_async16(st + row * ROWB + lc16 * 16,
                       A + (size_t)(bm + row) * K + k0 + lc16 * 8);
            int rB = bn + row; if (rB >= N) rB = N - 1;   // clamp; junk cols never stored
            cp_async16(st + TILE_BYTES + row * ROWB + lc16 * 16,
                       W + (size_t)rB * K + k0 + lc16 * 8);
        }
        cp_commit();
    };

    // per-lane ldmatrix base offsets (bytes, within a stage)
    // A x4 (m-tile i): lanes 0-15 rows wm+(lane&15) @k-half0, lanes 16-31 same rows @+16B
    const uint32_t aOff = (uint32_t)(wm + (lane & 15)) * ROWB + ((lane >> 4) << 4);
    // B x4 (pair p): covers n8-tiles 2p,2p+1
    const uint32_t bOff = TILE_BYTES
        + (uint32_t)(wn + ((lane >> 4) << 3) + (lane & 7)) * ROWB + (((lane >> 3) & 1) << 4);

    load_stage(0);
    load_stage(1);

    for (int kt = 0; kt < KT; kt++) {
        if (kt + 1 < KT) cp_wait<1>(); else cp_wait<0>();
        __syncthreads();                       // stage kt visible; stage (kt+2)%3 free
        if (kt + 2 < KT) load_stage(kt + 2);

        const uint32_t stg = smem_u + (kt % 3) * STG_BYTES;
        const uint32_t aB = stg + aOff;
        const uint32_t bB = stg + bOff;

        uint32_t Af[2][4][4], Bq[2][2][4];
#pragma unroll
        for (int i = 0; i < 4; i++) ldsm_x4(aB + (uint32_t)(i * 16 * ROWB), Af[0][i]);
#pragma unroll
        for (int p = 0; p < 2; p++) ldsm_x4(bB + (uint32_t)(p * 16 * ROWB), Bq[0][p]);

#pragma unroll
        for (int kk = 0; kk < 4; kk++) {       // 4 x k16 sub-steps (32B each)
            const int cur = kk & 1;
            if (kk < 3) {   // prefetch kk+1 fragments while cur's MMAs drain
                const uint32_t ko = (uint32_t)(kk + 1) * 32;
#pragma unroll
                for (int i = 0; i < 4; i++)
                    ldsm_x4(aB + ko + (uint32_t)(i * 16 * ROWB), Af[cur ^ 1][i]);
#pragma unroll
                for (int p = 0; p < 2; p++)
                    ldsm_x4(bB + ko + (uint32_t)(p * 16 * ROWB), Bq[cur ^ 1][p]);
            }
#pragma unroll
            for (int i = 0; i < 4; i++)
#pragma unroll
                for (int j = 0; j < 4; j++)
                    mma16816(acc[i][j], Af[cur][i], &Bq[cur][j >> 1][(j & 1) * 2]);
        }
    }

    // epilogue: direct float2 stores (+bias)
#pragma unroll
    for (int i = 0; i < 4; i++) {
        const int r0 = bm + wm + i * 16 + gid;
        const int r1 = r0 + 8;
#pragma unroll
        for (int j = 0; j < 4; j++) {
            const int c = wn + j * 8 + tig * 2;
            if (bn + c < N) {
                const float b0 = sBias[c], b1 = sBias[c + 1];
                float2 v0 = {acc[i][j][0] + b0, acc[i][j][1] + b1};
                float2 v1 = {acc[i][j][2] + b0, acc[i][j][3] + b1};
                *(float2*)(C + (size_t)r0 * N + bn + c) = v0;
                *(float2*)(C + (size_t)r1 * N + bn + c) = v1;
            }
        }
    }
}

// ---------------- fp32 -> fp16 rounding prepass (float4 in, 8B out) ----------
__global__ __launch_bounds__(256) void round_fp16_k(
    const float* __restrict__ in, __half* __restrict__ out, int n)
{
    int i = (blockIdx.x * 256 + threadIdx.x) * 4;
    if (i < n) {
        float4 v = *(const float4*)(in + i);
        __half2 h0 = __floats2half2_rn(v.x, v.y);
        __half2 h1 = __floats2half2_rn(v.z, v.w);
        *(__half2*)(out + i) = h0;
        *(__half2*)(out + i + 2) = h1;
    }
}

// ---------------- RMSNorm: fp32 in -> fp16 out ----------------
__global__ __launch_bounds__(256) void rmsnorm_fp16(
    const float* __restrict__ data, const float* __restrict__ w,
    __half* __restrict__ outp, int W)
{
    const int t = blockIdx.x, tid = threadIdx.x;
    const float* p = data + (size_t)t * W;
    __half* o = outp + (size_t)t * W;
    const int W4 = W >> 2;
    float ss = 0.f;
    for (int i = tid; i < W4; i += 256) {
        float4 v = ((const float4*)p)[i];
        ss += v.x * v.x + v.y * v.y + v.z * v.z + v.w * v.w;
    }
    __shared__ float red[256];
    red[tid] = ss; __syncthreads();
    for (int w2 = 128; w2 > 0; w2 >>= 1) {
        if (tid < w2) red[tid] += red[tid + w2];
        __syncthreads();
    }
    const float inv = rsqrtf(red[0] / (float)W + 1.1920929e-7f);
    for (int i = tid; i < W4; i += 256) {
        float4 v = ((const float4*)p)[i];
        const float4 g = ((const float4*)w)[i];
        __half2 h0 = __floats2half2_rn(v.x * inv * g.x, v.y * inv * g.y);
        __half2 h1 = __floats2half2_rn(v.z * inv * g.z, v.w * inv * g.w);
        *(__half2*)(o + i * 4) = h0;
        *(__half2*)(o + i * 4 + 2) = h1;
    }
}

// ---------------- kv_a post-process: rmsnorm(512)->fp16 + rope(last 64) ------
__global__ __launch_bounds__(128) void kv_prep(
    const float* __restrict__ kva, const float* __restrict__ knw,
    const float* __restrict__ cosb, const float* __restrict__ sinb,
    __half* __restrict__ kvn, float* __restrict__ kpe, int S)
{
    const int t = blockIdx.x, tid = threadIdx.x;
    const int s = t % S;
    const float* src = kva + (size_t)t * 576;
    float ss = 0.f;
    for (int i = tid; i < 512; i += 128) { float v = src[i]; ss += v * v; }
    __shared__ float red[128];
    red[tid] = ss; __syncthreads();
    for (int w2 = 64; w2 > 0; w2 >>= 1) {
        if (tid < w2) red[tid] += red[tid + w2];
        __syncthreads();
    }
    const float inv = rsqrtf(red[0] / 512.0f + 1.1920929e-7f);
    for (int i = tid; i < 512; i += 128)
        kvn[(size_t)t * 512 + i] = __float2half_rn(src[i] * inv * knw[i]);
    if (tid < 32) {
        const int j = tid;
        const float c = cosb[s * 32 + j], sn = sinb[s * 32 + j];
        const float x0 = src[512 + 2 * j], x1 = src[512 + 2 * j + 1];
        kpe[(size_t)t * 64 + 2 * j]     = x0 * c  - x1 * sn;
        kpe[(size_t)t * 64 + 2 * j + 1] = x0 * sn + x1 * c;
    }
}

// ---------------- per-token attention (fp16 output for wo GEMM) --------------
#define ATT_SCALE 0.07216878364870322f  // (128+64)^-0.5
__global__ __launch_bounds__(128) void attn_kernel(
    const float* __restrict__ q, const float* __restrict__ kv,
    const float* __restrict__ kpe, const float* __restrict__ cosb,
    const float* __restrict__ sinb, __half* __restrict__ out, int S)
{
    const int t = blockIdx.x, tid = threadIdx.x;
    const int s = t % S;
    __shared__ float qs[3072];
    __shared__ float kvs[16 * 260];
    __shared__ float kp[64];
    __shared__ float sc[16][17];

    const float* qg = q + (size_t)t * 3072;
    for (int i = tid; i < 768; i += 128) ((float4*)qs)[i] = ((const float4*)qg)[i];
    const float* kvg = kv + (size_t)t * 4096;
    for (int i = tid; i < 1024; i += 128) {
        int g = i >> 6, c = i & 63;
        *(float4*)&kvs[g * 260 + c * 4] = *(const float4*)(kvg + g * 256 + c * 4);
    }
    if (tid < 16) ((float4*)kp)[tid] = ((const float4*)(kpe + (size_t)t * 64))[tid];
    __syncthreads();

    for (int p = tid; p < 512; p += 128) {
        const int h = p >> 5, j = p & 31;
        const float c = cosb[s * 32 + j], sn = sinb[s * 32 + j];
        const int i0 = h * 192 + 128 + 2 * j;
        const float x0 = qs[i0], x1 = qs[i0 + 1];
        qs[i0]     = x0 * c  - x1 * sn;
        qs[i0 + 1] = x0 * sn + x1 * c;
    }
    __syncthreads();

    {
        const int h = tid >> 3, g0 = tid & 7, g1 = g0 + 8;
        const float* qh = &qs[h * 192];
        const float* k0 = &kvs[g0 * 260];
        const float* k1 = &kvs[g1 * 260];
        float a0 = 0.f, a1 = 0.f;
#pragma unroll 8
        for (int d = 0; d < 128; d++) { const float qd = qh[d]; a0 += qd * k0[d]; a1 += qd * k1[d]; }
        float pe = 0.f;
        const float* qp = &qs[h * 192 + 128];
#pragma unroll 8
        for (int d = 0; d < 64; d++) pe += qp[d] * kp[d];
        sc[h][g0] = (a0 + pe) * ATT_SCALE;
        sc[h][g1] = (a1 + pe) * ATT_SCALE;
    }
    __syncthreads();

    if (tid < 16) {
        float m = -1e30f;
#pragma unroll
        for (int g = 0; g < 16; g++) m = fmaxf(m, sc[tid][g]);
        float sum = 0.f;
#pragma unroll
        for (int g = 0; g < 16; g++) { const float e = expf(sc[tid][g] - m); sc[tid][g] = e; sum += e; }
        const float r = 1.f / sum;
#pragma unroll
        for (int g = 0; g < 16; g++) sc[tid][g] *= r;
    }
    __syncthreads();

    for (int o = tid; o < 2048; o += 128) {
        const int h = o >> 7, d = o & 127;
        float acc = 0.f;
#pragma unroll
        for (int g = 0; g < 16; g++) acc += sc[h][g] * kvs[g * 260 + 128 + d];
        out[(size_t)t * 2048 + o] = __float2half_rn(acc);
    }
}

// ---------------- host launcher ----------------
static inline void launch_gemm(const __half* A, const __half* W, const float* bias,
                               float* C, int M, int N, int K)
{
    dim3 grid((N + 127) / 128, M / 128);
    gemm_mma<<<grid, 256, GEMM_SMEM>>>(A, W, bias, C, M, N, K);
}
static inline void launch_round(const float* in, __half* out, int n)
{
    round_fp16_k<<<(n / 4 + 255) / 256, 256>>>(in, out, n);
}

extern "C" void kernel_launch(void* const* d_in, const int* in_sizes, int n_in,
                              void* d_out, int out_size)
{
    const float* x     = (const float*)d_in[0];
    const float* fcos  = (const float*)d_in[1];
    const float* fsin  = (const float*)d_in[2];
    const float* wqa   = (const float*)d_in[3];
    const float* wqab  = (const float*)d_in[4];
    const float* qnw   = (const float*)d_in[5];
    const float* wqb   = (const float*)d_in[6];
    const float* wqbb  = (const float*)d_in[7];
    const float* wkva  = (const float*)d_in[8];
    const float* wkvab = (const float*)d_in[9];
    const float* kvnw  = (const float*)d_in[10];
    const float* wkvb  = (const float*)d_in[11];
    const float* wkvbb = (const float*)d_in[12];
    const float* wo    = (const float*)d_in[13];
    const float* wob   = (const float*)d_in[14];
    float* out = (float*)d_out;

    const int T = in_sizes[0] / 2048;   // B*S tokens (8192)
    const int S = in_sizes[1] / 32;     // 2048

    float *qa, *qq, *kva, *kpe, *kv;
    __half *qah, *kvn, *ao, *xh, *wh;
    cudaGetSymbolAddress((void**)&qa,  g_qa);
    cudaGetSymbolAddress((void**)&qah, g_qah);
    cudaGetSymbolAddress((void**)&qq,  g_q);
    cudaGetSymbolAddress((void**)&kva, g_kva);
    cudaGetSymbolAddress((void**)&kvn, g_kvn);
    cudaGetSymbolAddress((void**)&kpe, g_kpe);
    cudaGetSymbolAddress((void**)&kv,  g_kv);
    cudaGetSymbolAddress((void**)&ao,  g_ao);
    cudaGetSymbolAddress((void**)&xh,  g_xh);
    cudaGetSymbolAddress((void**)&wh,  g_wh);

    cudaFuncSetAttribute(gemm_mma, cudaFuncAttributeMaxDynamicSharedMemorySize, GEMM_SMEM);

    // prepass: round x + all weights to fp16 (same mantissa width as tf32)
    launch_round(x,    xh,            T * 2048);
    launch_round(wqa,  wh + WQA_OFF,  1536 * 2048);
    launch_round(wqb,  wh + WQB_OFF,  3072 * 1536);
    launch_round(wkva, wh + WKVA_OFF, 576 * 2048);
    launch_round(wkvb, wh + WKVB_OFF, 4096 * 512);
    launch_round(wo,   wh + WO_OFF,   2048 * 2048);

    // q path
    launch_gemm(xh,  wh + WQA_OFF,  wqab,  qa,  T, 1536, 2048);
    rmsnorm_fp16<<<T, 256>>>(qa, qnw, qah, 1536);
    launch_gemm(qah, wh + WQB_OFF,  wqbb,  qq,  T, 3072, 1536);
    // kv path
    launch_gemm(xh,  wh + WKVA_OFF, wkvab, kva, T, 576,  2048);
    kv_prep<<<T, 128>>>(kva, kvnw, fcos, fsin, kvn, kpe, S);
    launch_gemm(kvn, wh + WKVB_OFF, wkvbb, kv,  T, 4096, 512);
    // attention + output projection
    attn_kernel<<<T, 128>>>(qq, kv, kpe, fcos, fsin, ao, S);
    launch_gemm(ao,  wh + WO_OFF,   wob,   out, T, 2048, 2048);
}

// round 13
// speedup vs baseline: 1.9570x; 1.6532x over previous
#include <cuda_runtime.h>
#include <cuda_fp16.h>
#include <cstdint>

// ---------------- scratch (allocation-free: __device__ globals) ----------------
#define T_TOK 8192
__device__ float  g_qa [T_TOK*1536];   // wq_a output (fp32)
__device__ __half g_qah[T_TOK*1536];   // rmsnorm(qa) in fp16
__device__ float  g_q  [T_TOK*3072];   // wq_b output (fp32, attention input)
__device__ float  g_kva[T_TOK*576];    // wkv_a output
__device__ __half g_kvn[T_TOK*512];    // normalized kv latent (fp16)
__device__ float  g_kpe[T_TOK*64];     // roped k_pe
__device__ float  g_kv [T_TOK*4096];   // wkv_b output (fp32)
__device__ __half g_ao [T_TOK*2048];   // attention output (fp16)
__device__ __half g_xh [T_TOK*2048];   // x in fp16
__device__ __half g_wh [15335424];     // all 5 weight matrices in fp16

#define WQA_OFF   0
#define WQB_OFF   3145728
#define WKVA_OFF  7864320
#define WKVB_OFF  9043968
#define WO_OFF    11141120

// ---------------- PTX helpers (arch-generic: sm_80+) ----------------
__device__ __forceinline__ void cp_async16(void* dst, const void* src) {
    unsigned s = (unsigned)__cvta_generic_to_shared(dst);
    asm volatile("cp.async.cg.shared.global [%0], [%1], 16;\n" :: "r"(s), "l"(src));
}
__device__ __forceinline__ void cp_commit() { asm volatile("cp.async.commit_group;\n"); }
template<int N> __device__ __forceinline__ void cp_wait() {
    asm volatile("cp.async.wait_group %0;\n" :: "n"(N));
}
__device__ __forceinline__ void mma16816(float* d, const uint32_t* a, const uint32_t* b) {
    asm volatile(
        "mma.sync.aligned.m16n8k16.row.col.f32.f16.f16.f32 "
        "{%0,%1,%2,%3}, {%4,%5,%6,%7}, {%8,%9}, {%0,%1,%2,%3};"
        : "+f"(d[0]), "+f"(d[1]), "+f"(d[2]), "+f"(d[3])
        : "r"(a[0]), "r"(a[1]), "r"(a[2]), "r"(a[3]), "r"(b[0]), "r"(b[1]));
}
__device__ __forceinline__ void ldsm_x4(uint32_t a, uint32_t* r) {
    asm volatile("ldmatrix.sync.aligned.m8n8.x4.shared.b16 {%0,%1,%2,%3}, [%4];"
        : "=r"(r[0]), "=r"(r[1]), "=r"(r[2]), "=r"(r[3]) : "r"(a));
}

// ---------------- fp16 mma.sync GEMM: C[M,N] = A[M,K] @ W[N,K]^T + bias[N] ---
// BM=BN=128, BK=64, 256 threads (8 warps 2x4), warp tile 64x32 (4x4 m16n8k16).
// fp32 accumulate. Row stride 72 halves (144B) keeps every 8-row ldmatrix
// phase conflict-free. 3-stage cp.async pipeline, one barrier per K-tile;
// fragment double-buffering across the 4 k16 sub-steps.
#define ROWB 144                          // bytes per smem row (72 halves)
#define TILE_BYTES (128 * ROWB)           // 18432 B per tile (A or B)
#define STG_BYTES (2 * TILE_BYTES)        // 36864 B per stage
#define GEMM_SMEM (3 * STG_BYTES + 512)   // 111104 B

__global__ __launch_bounds__(256, 2) void gemm_mma(
    const __half* __restrict__ A, const __half* __restrict__ W,
    const float* __restrict__ bias, float* __restrict__ C,
    int M, int N, int K)
{
    extern __shared__ char smem[];
    float* sBias = (float*)(smem + 3 * STG_BYTES);
    const uint32_t smem_u = (uint32_t)__cvta_generic_to_shared(smem);

    const int tid = threadIdx.x, warp = tid >> 5, lane = tid & 31;
    const int gid = lane >> 2, tig = lane & 3;
    const int bm = blockIdx.y * 128, bn = blockIdx.x * 128;
    const int wm = (warp >> 2) * 64, wn = (warp & 3) * 32;
    const int KT = K / 64;

    if (tid < 128) {
        int c = bn + tid;
        sBias[tid] = (c < N) ? bias[c] : 0.0f;
    }

    float acc[4][4][4];
#pragma unroll
    for (int i = 0; i < 4; i++)
#pragma unroll
        for (int j = 0; j < 4; j++)
#pragma unroll
            for (int r = 0; r < 4; r++) acc[i][j][r] = 0.0f;

    const int lrow = tid >> 3, lc16 = tid & 7;
    auto load_stage = [&](int kt) {
        char* st = smem + (kt % 3) * STG_BYTES;
        const int k0 = kt * 64;
#pragma unroll
        for (int i = 0; i < 4; i++) {
            const int row = lrow + i * 32;
            cp_async16(st + row * ROWB + lc16 * 16,
                       A + (size_t)(bm + row) * K + k0 + lc16 * 8);
            int rB = bn + row; if (rB >= N) rB = N - 1;   // clamp; junk cols never stored
            cp_async16(st + TILE_BYTES + row * ROWB + lc16 * 16,
                       W + (size_t)rB * K + k0 + lc16 * 8);
        }
        cp_commit();
    };

    const uint32_t aOff = (uint32_t)(wm + (lane & 15)) * ROWB + ((lane >> 4) << 4);
    const uint32_t bOff = TILE_BYTES
        + (uint32_t)(wn + ((lane >> 4) << 3) + (lane & 7)) * ROWB + (((lane >> 3) & 1) << 4);

    load_stage(0);
    load_stage(1);

    for (int kt = 0; kt < KT; kt++) {
        if (kt + 1 < KT) cp_wait<1>(); else cp_wait<0>();
        __syncthreads();                       // stage kt visible; stage (kt+2)%3 free
        if (kt + 2 < KT) load_stage(kt + 2);

        const uint32_t stg = smem_u + (kt % 3) * STG_BYTES;
        const uint32_t aB = stg + aOff;
        const uint32_t bB = stg + bOff;

        uint32_t Af[2][4][4], Bq[2][2][4];
#pragma unroll
        for (int i = 0; i < 4; i++) ldsm_x4(aB + (uint32_t)(i * 16 * ROWB), Af[0][i]);
#pragma unroll
        for (int p = 0; p < 2; p++) ldsm_x4(bB + (uint32_t)(p * 16 * ROWB), Bq[0][p]);

#pragma unroll
        for (int kk = 0; kk < 4; kk++) {       // 4 x k16 sub-steps (32B each)
            const int cur = kk & 1;
            if (kk < 3) {   // prefetch kk+1 fragments while cur's MMAs drain
                const uint32_t ko = (uint32_t)(kk + 1) * 32;
#pragma unroll
                for (int i = 0; i < 4; i++)
                    ldsm_x4(aB + ko + (uint32_t)(i * 16 * ROWB), Af[cur ^ 1][i]);
#pragma unroll
                for (int p = 0; p < 2; p++)
                    ldsm_x4(bB + ko + (uint32_t)(p * 16 * ROWB), Bq[cur ^ 1][p]);
            }
#pragma unroll
            for (int i = 0; i < 4; i++)
#pragma unroll
                for (int j = 0; j < 4; j++)
                    mma16816(acc[i][j], Af[cur][i], &Bq[cur][j >> 1][(j & 1) * 2]);
        }
    }

    // epilogue: direct float2 stores (+bias)
#pragma unroll
    for (int i = 0; i < 4; i++) {
        const int r0 = bm + wm + i * 16 + gid;
        const int r1 = r0 + 8;
#pragma unroll
        for (int j = 0; j < 4; j++) {
            const int c = wn + j * 8 + tig * 2;
            if (bn + c < N) {
                const float b0 = sBias[c], b1 = sBias[c + 1];
                float2 v0 = {acc[i][j][0] + b0, acc[i][j][1] + b1};
                float2 v1 = {acc[i][j][2] + b0, acc[i][j][3] + b1};
                *(float2*)(C + (size_t)r0 * N + bn + c) = v0;
                *(float2*)(C + (size_t)r1 * N + bn + c) = v1;
            }
        }
    }
}

// ---------------- fp32 -> fp16 rounding prepass (float4 in, 8B out) ----------
__global__ __launch_bounds__(256) void round_fp16_k(
    const float* __restrict__ in, __half* __restrict__ out, int n)
{
    int i = (blockIdx.x * 256 + threadIdx.x) * 4;
    if (i < n) {
        float4 v = *(const float4*)(in + i);
        __half2 h0 = __floats2half2_rn(v.x, v.y);
        __half2 h1 = __floats2half2_rn(v.z, v.w);
        *(__half2*)(out + i) = h0;
        *(__half2*)(out + i + 2) = h1;
    }
}

// ---------------- RMSNorm: fp32 in -> fp16 out ----------------
__global__ __launch_bounds__(256) void rmsnorm_fp16(
    const float* __restrict__ data, const float* __restrict__ w,
    __half* __restrict__ outp, int W)
{
    const int t = blockIdx.x, tid = threadIdx.x;
    const float* p = data + (size_t)t * W;
    __half* o = outp + (size_t)t * W;
    const int W4 = W >> 2;
    float ss = 0.f;
    for (int i = tid; i < W4; i += 256) {
        float4 v = ((const float4*)p)[i];
        ss += v.x * v.x + v.y * v.y + v.z * v.z + v.w * v.w;
    }
    __shared__ float red[256];
    red[tid] = ss; __syncthreads();
    for (int w2 = 128; w2 > 0; w2 >>= 1) {
        if (tid < w2) red[tid] += red[tid + w2];
        __syncthreads();
    }
    const float inv = rsqrtf(red[0] / (float)W + 1.1920929e-7f);
    for (int i = tid; i < W4; i += 256) {
        float4 v = ((const float4*)p)[i];
        const float4 g = ((const float4*)w)[i];
        __half2 h0 = __floats2half2_rn(v.x * inv * g.x, v.y * inv * g.y);
        __half2 h1 = __floats2half2_rn(v.z * inv * g.z, v.w * inv * g.w);
        *(__half2*)(o + i * 4) = h0;
        *(__half2*)(o + i * 4 + 2) = h1;
    }
}

// ---------------- kv_a post-process: rmsnorm(512)->fp16 + rope(last 64) ------
__global__ __launch_bounds__(128) void kv_prep(
    const float* __restrict__ kva, const float* __restrict__ knw,
    const float* __restrict__ cosb, const float* __restrict__ sinb,
    __half* __restrict__ kvn, float* __restrict__ kpe, int S)
{
    const int t = blockIdx.x, tid = threadIdx.x;
    const int s = t % S;
    const float* src = kva + (size_t)t * 576;
    float ss = 0.f;
    for (int i = tid; i < 512; i += 128) { float v = src[i]; ss += v * v; }
    __shared__ float red[128];
    red[tid] = ss; __syncthreads();
    for (int w2 = 64; w2 > 0; w2 >>= 1) {
        if (tid < w2) red[tid] += red[tid + w2];
        __syncthreads();
    }
    const float inv = rsqrtf(red[0] / 512.0f + 1.1920929e-7f);
    for (int i = tid; i < 512; i += 128)
        kvn[(size_t)t * 512 + i] = __float2half_rn(src[i] * inv * knw[i]);
    if (tid < 32) {
        const int j = tid;
        const float c = cosb[s * 32 + j], sn = sinb[s * 32 + j];
        const float x0 = src[512 + 2 * j], x1 = src[512 + 2 * j + 1];
        kpe[(size_t)t * 64 + 2 * j]     = x0 * c  - x1 * sn;
        kpe[(size_t)t * 64 + 2 * j + 1] = x0 * sn + x1 * c;
    }
}

// ---------------- per-token attention (fp16 output for wo GEMM) --------------
#define ATT_SCALE 0.07216878364870322f  // (128+64)^-0.5
__global__ __launch_bounds__(128) void attn_kernel(
    const float* __restrict__ q, const float* __restrict__ kv,
    const float* __restrict__ kpe, const float* __restrict__ cosb,
    const float* __restrict__ sinb, __half* __restrict__ out, int S)
{
    const int t = blockIdx.x, tid = threadIdx.x;
    const int s = t % S;
    __shared__ float qs[3072];
    __shared__ float kvs[16 * 260];
    __shared__ float kp[64];
    __shared__ float sc[16][17];

    const float* qg = q + (size_t)t * 3072;
    for (int i = tid; i < 768; i += 128) ((float4*)qs)[i] = ((const float4*)qg)[i];
    const float* kvg = kv + (size_t)t * 4096;
    for (int i = tid; i < 1024; i += 128) {
        int g = i >> 6, c = i & 63;
        *(float4*)&kvs[g * 260 + c * 4] = *(const float4*)(kvg + g * 256 + c * 4);
    }
    if (tid < 16) ((float4*)kp)[tid] = ((const float4*)(kpe + (size_t)t * 64))[tid];
    __syncthreads();

    for (int p = tid; p < 512; p += 128) {
        const int h = p >> 5, j = p & 31;
        const float c = cosb[s * 32 + j], sn = sinb[s * 32 + j];
        const int i0 = h * 192 + 128 + 2 * j;
        const float x0 = qs[i0], x1 = qs[i0 + 1];
        qs[i0]     = x0 * c  - x1 * sn;
        qs[i0 + 1] = x0 * sn + x1 * c;
    }
    __syncthreads();

    {
        const int h = tid >> 3, g0 = tid & 7, g1 = g0 + 8;
        const float* qh = &qs[h * 192];
        const float* k0 = &kvs[g0 * 260];
        const float* k1 = &kvs[g1 * 260];
        float a0 = 0.f, a1 = 0.f;
#pragma unroll 8
        for (int d = 0; d < 128; d++) { const float qd = qh[d]; a0 += qd * k0[d]; a1 += qd * k1[d]; }
        float pe = 0.f;
        const float* qp = &qs[h * 192 + 128];
#pragma unroll 8
        for (int d = 0; d < 64; d++) pe += qp[d] * kp[d];
        sc[h][g0] = (a0 + pe) * ATT_SCALE;
        sc[h][g1] = (a1 + pe) * ATT_SCALE;
    }
    __syncthreads();

    if (tid < 16) {
        float m = -1e30f;
#pragma unroll
        for (int g = 0; g < 16; g++) m = fmaxf(m, sc[tid][g]);
        float sum = 0.f;
#pragma unroll
        for (int g = 0; g < 16; g++) { const float e = expf(sc[tid][g] - m); sc[tid][g] = e; sum += e; }
        const float r = 1.f / sum;
#pragma unroll
        for (int g = 0; g < 16; g++) sc[tid][g] *= r;
    }
    __syncthreads();

    for (int o = tid; o < 2048; o += 128) {
        const int h = o >> 7, d = o & 127;
        float acc = 0.f;
#pragma unroll
        for (int g = 0; g < 16; g++) acc += sc[h][g] * kvs[g * 260 + 128 + d];
        out[(size_t)t * 2048 + o] = __float2half_rn(acc);
    }
}

// ---------------- host launcher (dual-stream fork/join, capture-safe) --------
static inline void launch_gemm_s(cudaStream_t st, const __half* A, const __half* W,
                                 const float* bias, float* C, int M, int N, int K)
{
    dim3 grid((N + 127) / 128, M / 128);
    gemm_mma<<<grid, 256, GEMM_SMEM, st>>>(A, W, bias, C, M, N, K);
}
static inline void launch_round_s(cudaStream_t st, const float* in, __half* out, int n)
{
    round_fp16_k<<<(n / 4 + 255) / 256, 256, 0, st>>>(in, out, n);
}

extern "C" void kernel_launch(void* const* d_in, const int* in_sizes, int n_in,
                              void* d_out, int out_size)
{
    const float* x     = (const float*)d_in[0];
    const float* fcos  = (const float*)d_in[1];
    const float* fsin  = (const float*)d_in[2];
    const float* wqa   = (const float*)d_in[3];
    const float* wqab  = (const float*)d_in[4];
    const float* qnw   = (const float*)d_in[5];
    const float* wqb   = (const float*)d_in[6];
    const float* wqbb  = (const float*)d_in[7];
    const float* wkva  = (const float*)d_in[8];
    const float* wkvab = (const float*)d_in[9];
    const float* kvnw  = (const float*)d_in[10];
    const float* wkvb  = (const float*)d_in[11];
    const float* wkvbb = (const float*)d_in[12];
    const float* wo    = (const float*)d_in[13];
    const float* wob   = (const float*)d_in[14];
    float* out = (float*)d_out;

    const int T = in_sizes[0] / 2048;   // B*S tokens (8192)
    const int S = in_sizes[1] / 32;     // 2048

    float *qa, *qq, *kva, *kpe, *kv;
    __half *qah, *kvn, *ao, *xh, *wh;
    cudaGetSymbolAddress((void**)&qa,  g_qa);
    cudaGetSymbolAddress((void**)&qah, g_qah);
    cudaGetSymbolAddress((void**)&qq,  g_q);
    cudaGetSymbolAddress((void**)&kva, g_kva);
    cudaGetSymbolAddress((void**)&kvn, g_kvn);
    cudaGetSymbolAddress((void**)&kpe, g_kpe);
    cudaGetSymbolAddress((void**)&kv,  g_kv);
    cudaGetSymbolAddress((void**)&ao,  g_ao);
    cudaGetSymbolAddress((void**)&xh,  g_xh);
    cudaGetSymbolAddress((void**)&wh,  g_wh);

    cudaFuncSetAttribute(gemm_mma, cudaFuncAttributeMaxDynamicSharedMemorySize, GEMM_SMEM);

    // Host-side stream/event handles, created once on the (uncaptured)
    // correctness call; no device memory involved. Every call records the
    // identical fork/join DAG, so each capture yields the same graph.
    static cudaStream_t s1 = nullptr;
    static cudaEvent_t eFork, eX, eWQB, eKV;
    if (s1 == nullptr) {
        cudaStreamCreateWithFlags(&s1, cudaStreamNonBlocking);
        cudaEventCreateWithFlags(&eFork, cudaEventDisableTiming);
        cudaEventCreateWithFlags(&eX,    cudaEventDisableTiming);
        cudaEventCreateWithFlags(&eWQB,  cudaEventDisableTiming);
        cudaEventCreateWithFlags(&eKV,   cudaEventDisableTiming);
    }
    cudaStream_t d = 0;                 // capture-origin (legacy default) stream

    // fork s1 off the capture stream
    cudaEventRecord(eFork, d);
    cudaStreamWaitEvent(s1, eFork, 0);

    // ---- default stream: q path ----
    launch_round_s(d, x, xh, T * 2048);
    cudaEventRecord(eX, d);                               // xh ready
    launch_round_s(d, wqa, wh + WQA_OFF, 1536 * 2048);
    launch_gemm_s(d, xh, wh + WQA_OFF, wqab, qa, T, 1536, 2048);
    rmsnorm_fp16<<<T, 256, 0, d>>>(qa, qnw, qah, 1536);

    // ---- s1: remaining weight rounds + kv path ----
    launch_round_s(s1, wqb, wh + WQB_OFF, 3072 * 1536);
    cudaEventRecord(eWQB, s1);                            // wqb(h) ready
    launch_round_s(s1, wkva, wh + WKVA_OFF, 576 * 2048);
    launch_round_s(s1, wkvb, wh + WKVB_OFF, 4096 * 512);
    launch_round_s(s1, wo,   wh + WO_OFF,   2048 * 2048);
    cudaStreamWaitEvent(s1, eX, 0);                       // needs xh
    launch_gemm_s(s1, xh, wh + WKVA_OFF, wkvab, kva, T, 576, 2048);
    kv_prep<<<T, 128, 0, s1>>>(kva, kvnw, fcos, fsin, kvn, kpe, S);
    launch_gemm_s(s1, kvn, wh + WKVB_OFF, wkvbb, kv, T, 4096, 512);
    cudaEventRecord(eKV, s1);                             // kv path done (incl. wo round)

    // ---- default stream: wq_b, then join and finish ----
    cudaStreamWaitEvent(d, eWQB, 0);
    launch_gemm_s(d, qah, wh + WQB_OFF, wqbb, qq, T, 3072, 1536);
    cudaStreamWaitEvent(d, eKV, 0);                       // join s1
    attn_kernel<<<T, 128, 0, d>>>(qq, kv, kpe, fcos, fsin, ao, S);
    launch_gemm_s(d, ao, wh + WO_OFF, wob, out, T, 2048, 2048);
}